// round 8
// baseline (speedup 1.0000x reference)
#include <cuda_runtime.h>
#include <cuda_bf16.h>

// Problem constants
#define B_   8
#define LQ_  512
#define LK_  512
#define D_   512
#define H_   128
#define M_   (B_ * LQ_)   // 4096 rows per projection

// Scratch for projected Q and K (no cudaMalloc allowed)
__device__ float g_Q[M_ * H_];
__device__ float g_K[M_ * H_];

__device__ __forceinline__ float fast_tanh(float x) {
    float y;
    asm("tanh.approx.f32 %0, %1;" : "=f"(y) : "f"(x));
    return y;
}

// Packed fp32x2 FMA (Blackwell FFMA2) — IEEE fp32 fused, bit-identical to fmaf.
__device__ __forceinline__ unsigned long long fma_f32x2(
    unsigned long long a, unsigned long long b, unsigned long long c) {
    unsigned long long d;
    asm("fma.rn.f32x2 %0, %1, %2, %3;" : "=l"(d) : "l"(a), "l"(b), "l"(c));
    return d;
}
__device__ __forceinline__ void unpack2(unsigned long long p, float& lo, float& hi) {
    asm("mov.b64 {%0, %1}, %2;" : "=f"(lo), "=f"(hi) : "l"(p));
}

// ---------------------------------------------------------------------------
// Projection GEMM: Y[m, h] = sum_d X[m, d] * W[d, h]
// M=4096 (x2), K=512, N=128.  BM=64, BN=128, BK=16, 256 thr, 128 blocks.
// Key trick: zero pack-MOVs in the inner loop.
//   - accumulators pair COLUMNS: acc[i][jp] = (Y[r_i][2jp], Y[r_i][2jp+1]);
//     B pairs read directly from Bs as 64-bit words.
//   - A is stored DUPLICATED in shared (As2[k][2m]=As2[k][2m+1]=a), so the
//     (a,a) operand arrives via broadcast LDS.128 (2 dup-rows per load).
// Inner loop per kk: 4 bcast LDS.128 (A) + 1 LDS.128 (B) + 16 FFMA2.
// ---------------------------------------------------------------------------
#define BM 64
#define BK 16
#define BN 128

__global__ __launch_bounds__(256) void proj_kernel(
    const float* __restrict__ qs, const float* __restrict__ ks,
    const float* __restrict__ Wq, const float* __restrict__ Wk)
{
    const int nb = M_ / BM;                 // 64 blocks per projection
    bool isK = (blockIdx.x >= nb);
    int bm = isK ? (blockIdx.x - nb) : blockIdx.x;
    const float* __restrict__ X = isK ? ks : qs;
    const float* __restrict__ W = isK ? Wk : Wq;
    float* __restrict__ Y = isK ? g_K : g_Q;

    __shared__ float As2[BK][2 * BM];   // duplicated A: [k][2m],[2m+1] = a
    __shared__ float Bs[BK][BN];

    int tid = threadIdx.x;
    int tx = tid & 31;       // col group: cols tx*4 .. +3  (2 pairs)
    int ty = tid >> 5;       // row group: rows ty*8 .. +7

    int ar  = tid >> 2, ac4 = tid & 3;     // A load: 64x16 = 256 float4
    int br  = tid >> 5, bc4 = tid & 31;    // B load: rows br, br+8

    const float* Xp  = X + (size_t)(bm * BM + ar) * D_ + ac4 * 4;
    const float* Wp0 = W + (size_t)br * BN + bc4 * 4;
    const float* Wp1 = W + (size_t)(br + 8) * BN + bc4 * 4;

    unsigned long long acc2[8][2];     // [row i][col pair jp]
#pragma unroll
    for (int i = 0; i < 8; i++) { acc2[i][0] = 0ull; acc2[i][1] = 0ull; }

    // Prefetch first tiles into registers
    float4 pa  = *(const float4*)(Xp);
    float4 pb0 = *(const float4*)(Wp0);
    float4 pb1 = *(const float4*)(Wp1);

    for (int k0 = 0; k0 < D_; k0 += BK) {
        // Stage into shared: A duplicated
        {
            float2* d0 = (float2*)&As2[ac4 * 4 + 0][2 * ar];
            float2* d1 = (float2*)&As2[ac4 * 4 + 1][2 * ar];
            float2* d2 = (float2*)&As2[ac4 * 4 + 2][2 * ar];
            float2* d3 = (float2*)&As2[ac4 * 4 + 3][2 * ar];
            *d0 = make_float2(pa.x, pa.x);
            *d1 = make_float2(pa.y, pa.y);
            *d2 = make_float2(pa.z, pa.z);
            *d3 = make_float2(pa.w, pa.w);
        }
        *(float4*)(&Bs[br][bc4 * 4])     = pb0;
        *(float4*)(&Bs[br + 8][bc4 * 4]) = pb1;
        __syncthreads();

        // Prefetch next tiles (hidden under compute)
        if (k0 + BK < D_) {
            pa  = *(const float4*)(Xp + k0 + BK);
            pb0 = *(const float4*)(Wp0 + (size_t)(k0 + BK) * BN);
            pb1 = *(const float4*)(Wp1 + (size_t)(k0 + BK) * BN);
        }

#pragma unroll
        for (int kk = 0; kk < BK; ++kk) {
            // A dup-pairs: 4 broadcast LDS.128, each = rows (2i, 2i+1) dup'd
            ulonglong2 a01 = *(const ulonglong2*)(&As2[kk][2 * (ty * 8) + 0]);
            ulonglong2 a23 = *(const ulonglong2*)(&As2[kk][2 * (ty * 8) + 4]);
            ulonglong2 a45 = *(const ulonglong2*)(&As2[kk][2 * (ty * 8) + 8]);
            ulonglong2 a67 = *(const ulonglong2*)(&As2[kk][2 * (ty * 8) + 12]);
            unsigned long long ad[8] = {a01.x, a01.y, a23.x, a23.y,
                                        a45.x, a45.y, a67.x, a67.y};
            // B col-pairs: one LDS.128 = pairs (b0,b1),(b2,b3)
            ulonglong2 bp = *(const ulonglong2*)(&Bs[kk][tx * 4]);
#pragma unroll
            for (int i = 0; i < 8; i++) {
                acc2[i][0] = fma_f32x2(ad[i], bp.x, acc2[i][0]);
                acc2[i][1] = fma_f32x2(ad[i], bp.y, acc2[i][1]);
            }
        }
        __syncthreads();
    }

    // Epilogue: row ty*8+i, cols tx*4..+3 (pairs contiguous)
#pragma unroll
    for (int i = 0; i < 8; i++) {
        float c0, c1, c2, c3;
        unpack2(acc2[i][0], c0, c1);
        unpack2(acc2[i][1], c2, c3);
        *(float4*)(Y + (size_t)(bm * BM + ty * 8 + i) * H_ + tx * 4) =
            make_float4(c0, c1, c2, c3);
    }
}

// ---------------------------------------------------------------------------
// Score kernel: out[b,q,k] = sum_h wv[h] * tanh(Q[b,q,h] + K[b,k,h])
// 512 blocks x 2 consecutive tiles (32q x 64k) -> at most one wave at occ>=4.
// MUFU-bound core unchanged.
// ---------------------------------------------------------------------------
#define TQ 32
#define TK 64

__global__ __launch_bounds__(256) void score_kernel(
    const float* __restrict__ wv, float* __restrict__ out)
{
    __shared__ float sq[TQ][65];
    __shared__ float sk[TK][65];
    __shared__ float swv[H_];

    int tid = threadIdx.x;
    int tx = tid & 15;
    int ty = tid >> 4;
    if (tid < H_) swv[tid] = wv[tid];

#pragma unroll
    for (int it = 0; it < 2; ++it) {
        int s  = (blockIdx.x << 1) | it;
        int b  = s >> 7;
        int w  = s & 127;
        int q0 = (w >> 3) * TQ;
        int k0 = (w & 7) * TK;

        const float* Qb = g_Q + (size_t)(b * LQ_ + q0) * H_;
        const float* Kb = g_K + (size_t)(b * LK_ + k0) * H_;

        float acc[2][4];
#pragma unroll
        for (int i = 0; i < 2; i++)
#pragma unroll
            for (int j = 0; j < 4; j++) acc[i][j] = 0.f;

#pragma unroll
        for (int half = 0; half < 2; ++half) {
            __syncthreads();
            for (int i = tid; i < 512; i += 256) {
                int r = i >> 4, c4 = i & 15;
                float4 v = *(const float4*)(Qb + r * H_ + half * 64 + c4 * 4);
                float* dq = &sq[r][c4 * 4];
                dq[0] = v.x; dq[1] = v.y; dq[2] = v.z; dq[3] = v.w;
            }
            for (int i = tid; i < 1024; i += 256) {
                int r = i >> 4, c4 = i & 15;
                float4 u = *(const float4*)(Kb + r * H_ + half * 64 + c4 * 4);
                float* dk = &sk[r][c4 * 4];
                dk[0] = u.x; dk[1] = u.y; dk[2] = u.z; dk[3] = u.w;
            }
            __syncthreads();

#pragma unroll 4
            for (int h = 0; h < 64; ++h) {
                float wvh = swv[half * 64 + h];
                float qv[2], kv[4];
#pragma unroll
                for (int i = 0; i < 2; i++) qv[i] = sq[ty + 16 * i][h];
#pragma unroll
                for (int j = 0; j < 4; j++) kv[j] = sk[tx + 16 * j][h];
#pragma unroll
                for (int i = 0; i < 2; i++)
#pragma unroll
                    for (int j = 0; j < 4; j++)
                        acc[i][j] = fmaf(wvh, fast_tanh(qv[i] + kv[j]), acc[i][j]);
            }
        }

        float* ob = out + ((size_t)b * LQ_ + q0) * LK_ + k0;
#pragma unroll
        for (int i = 0; i < 2; i++)
#pragma unroll
            for (int j = 0; j < 4; j++)
                ob[(size_t)(ty + 16 * i) * LK_ + tx + 16 * j] = acc[i][j];
        __syncthreads();
    }
}

// ---------------------------------------------------------------------------

extern "C" void kernel_launch(void* const* d_in, const int* in_sizes, int n_in,
                              void* d_out, int out_size)
{
    const float* qs = (const float*)d_in[0];   // [8,512,512]
    const float* ks = (const float*)d_in[1];   // [8,512,512]
    const float* Wq = (const float*)d_in[2];   // [512,128]
    const float* Wk = (const float*)d_in[3];   // [512,128]
    const float* wv = (const float*)d_in[4];   // [128]
    float* out = (float*)d_out;                // [8,512,512]

    proj_kernel<<<2 * (M_ / BM), 256>>>(qs, ks, Wq, Wk);
    score_kernel<<<512, 256>>>(wv, out);
}

// round 9
// speedup vs baseline: 1.1526x; 1.1526x over previous
#include <cuda_runtime.h>
#include <cuda_bf16.h>

// Problem constants
#define B_   8
#define LQ_  512
#define LK_  512
#define D_   512
#define H_   128
#define M_   (B_ * LQ_)   // 4096 rows per projection

// Scratch for projected Q and K (no cudaMalloc allowed)
__device__ float g_Q[M_ * H_];
__device__ float g_K[M_ * H_];

__device__ __forceinline__ float fast_tanh(float x) {
    float y;
    asm("tanh.approx.f32 %0, %1;" : "=f"(y) : "f"(x));
    return y;
}

// Packed fp32x2 FMA (Blackwell FFMA2) — IEEE fp32 fused, bit-identical to fmaf.
__device__ __forceinline__ unsigned long long fma_f32x2(
    unsigned long long a, unsigned long long b, unsigned long long c) {
    unsigned long long d;
    asm("fma.rn.f32x2 %0, %1, %2, %3;" : "=l"(d) : "l"(a), "l"(b), "l"(c));
    return d;
}
__device__ __forceinline__ unsigned long long pack2(float lo, float hi) {
    unsigned long long p;
    asm("mov.b64 %0, {%1, %2};" : "=l"(p) : "f"(lo), "f"(hi));
    return p;
}
__device__ __forceinline__ void unpack2(unsigned long long p, float& lo, float& hi) {
    asm("mov.b64 {%0, %1}, %2;" : "=f"(lo), "=f"(hi) : "l"(p));
}

// ---------------------------------------------------------------------------
// Projection GEMM: Y[m, h] = sum_d X[m, d] * W[d, h]
// M=4096 (x2), K=512, N=128.  BM=64, BN=128, BK=16 — SAME tiles/traffic as
// the 32us version, but 512 threads/block: 16 warps/SM (4/SMSP) so LDS
// latency and BAR are actually hidden. Thread tile 4 rows (2 f32x2 row-pairs)
// x 4 cols = 8 FFMA2/kk; A row-pairs from transposed As via broadcast
// LDS.128, B scalars dup-packed (4 MOVs/kk on the alu pipe, non-binding).
// ---------------------------------------------------------------------------
#define BM 64
#define BK 16
#define BN 128
#define APAD 8   // As row stride 72 floats

__global__ __launch_bounds__(512) void proj_kernel(
    const float* __restrict__ qs, const float* __restrict__ ks,
    const float* __restrict__ Wq, const float* __restrict__ Wk)
{
    const int nb = M_ / BM;                 // 64 blocks per projection
    bool isK = (blockIdx.x >= nb);
    int bm = isK ? (blockIdx.x - nb) : blockIdx.x;
    const float* __restrict__ X = isK ? ks : qs;
    const float* __restrict__ W = isK ? Wk : Wq;
    float* __restrict__ Y = isK ? g_K : g_Q;

    __shared__ float As[BK][BM + APAD];  // transposed: As[k][m]
    __shared__ float Bs[BK][BN];

    int tid = threadIdx.x;
    int tx = tid & 31;       // col group: cols tx*4 .. +3
    int ty = tid >> 5;       // row group: rows ty*4 .. +3  (16 groups)

    // A tile 64x16 = 256 float4: threads 0..255, one each
    int ar  = (tid & 255) >> 2;
    int ac4 = tid & 3;
    // B tile 16x128 = 512 float4: one per thread
    int br  = tid >> 5;      // k-row 0..15
    int bc4 = tid & 31;      // col group

    const float* Xp = X + (size_t)(bm * BM + ar) * D_ + ac4 * 4;
    const float* Wp = W + (size_t)br * BN + bc4 * 4;

    unsigned long long acc2[2][4];   // [row pair i][col j]
#pragma unroll
    for (int i = 0; i < 2; i++)
#pragma unroll
        for (int j = 0; j < 4; j++) acc2[i][j] = 0ull;

    // Prefetch first tiles into registers
    float4 pa = (tid < 256) ? *(const float4*)(Xp) : make_float4(0, 0, 0, 0);
    float4 pb = *(const float4*)(Wp);

    for (int k0 = 0; k0 < D_; k0 += BK) {
        // Stage prefetched tiles into shared
        if (tid < 256) {
            As[ac4 * 4 + 0][ar] = pa.x;
            As[ac4 * 4 + 1][ar] = pa.y;
            As[ac4 * 4 + 2][ar] = pa.z;
            As[ac4 * 4 + 3][ar] = pa.w;
        }
        *(float4*)(&Bs[br][bc4 * 4]) = pb;
        __syncthreads();

        // Prefetch next tiles (hidden under compute)
        if (k0 + BK < D_) {
            if (tid < 256) pa = *(const float4*)(Xp + k0 + BK);
            pb = *(const float4*)(Wp + (size_t)(k0 + BK) * BN);
        }

#pragma unroll
        for (int kk = 0; kk < BK; ++kk) {
            // 2 packed row-pairs via one broadcast LDS.128
            ulonglong2 a01 = *(const ulonglong2*)(&As[kk][ty * 4]);
            unsigned long long ap[2] = {a01.x, a01.y};
            float4 bv = *(const float4*)(&Bs[kk][tx * 4]);
            unsigned long long bd[4] = {
                pack2(bv.x, bv.x), pack2(bv.y, bv.y),
                pack2(bv.z, bv.z), pack2(bv.w, bv.w)};
#pragma unroll
            for (int i = 0; i < 2; i++)
#pragma unroll
                for (int j = 0; j < 4; j++)
                    acc2[i][j] = fma_f32x2(ap[i], bd[j], acc2[i][j]);
        }
        __syncthreads();
    }

    // Epilogue: acc2[i][j] = rows (ty*4+2i, +1), cols tx*4..+3
#pragma unroll
    for (int i = 0; i < 2; i++) {
        float lo[4], hi[4];
#pragma unroll
        for (int j = 0; j < 4; j++) unpack2(acc2[i][j], lo[j], hi[j]);
        size_t r0 = (size_t)(bm * BM + ty * 4 + 2 * i) * H_ + tx * 4;
        *(float4*)(Y + r0)      = make_float4(lo[0], lo[1], lo[2], lo[3]);
        *(float4*)(Y + r0 + H_) = make_float4(hi[0], hi[1], hi[2], hi[3]);
    }
}

// ---------------------------------------------------------------------------
// Score kernel: out[b,q,k] = sum_h wv[h] * tanh(Q[b,q,h] + K[b,k,h])
// 32q x 64k tiles, 256 threads, thread tile 2x4. 1024 blocks — the measured
// best (65.2us, ~92% of the MUFU roofline). Exactly the R2 kernel.
// ---------------------------------------------------------------------------
#define TQ 32
#define TK 64

__global__ __launch_bounds__(256) void score_kernel(
    const float* __restrict__ wv, float* __restrict__ out)
{
    __shared__ float sq[TQ][65];
    __shared__ float sk[TK][65];
    __shared__ float swv[H_];

    int b  = blockIdx.z;
    int q0 = blockIdx.y * TQ;
    int k0 = blockIdx.x * TK;

    const float* Qb = g_Q + (size_t)(b * LQ_ + q0) * H_;
    const float* Kb = g_K + (size_t)(b * LK_ + k0) * H_;

    int tid = threadIdx.x;
    if (tid < H_) swv[tid] = wv[tid];

    int tx = tid & 15;
    int ty = tid >> 4;

    float acc[2][4];
#pragma unroll
    for (int i = 0; i < 2; i++)
#pragma unroll
        for (int j = 0; j < 4; j++) acc[i][j] = 0.f;

#pragma unroll
    for (int half = 0; half < 2; ++half) {
        __syncthreads();
        for (int i = tid; i < 512; i += 256) {
            int r = i >> 4, c4 = i & 15;
            float4 v = *(const float4*)(Qb + r * H_ + half * 64 + c4 * 4);
            float* dq = &sq[r][c4 * 4];
            dq[0] = v.x; dq[1] = v.y; dq[2] = v.z; dq[3] = v.w;
        }
        for (int i = tid; i < 1024; i += 256) {
            int r = i >> 4, c4 = i & 15;
            float4 w = *(const float4*)(Kb + r * H_ + half * 64 + c4 * 4);
            float* dk = &sk[r][c4 * 4];
            dk[0] = w.x; dk[1] = w.y; dk[2] = w.z; dk[3] = w.w;
        }
        __syncthreads();

#pragma unroll 4
        for (int h = 0; h < 64; ++h) {
            float wvh = swv[half * 64 + h];
            float qv[2], kv[4];
#pragma unroll
            for (int i = 0; i < 2; i++) qv[i] = sq[ty + 16 * i][h];
#pragma unroll
            for (int j = 0; j < 4; j++) kv[j] = sk[tx + 16 * j][h];
#pragma unroll
            for (int i = 0; i < 2; i++)
#pragma unroll
                for (int j = 0; j < 4; j++)
                    acc[i][j] = fmaf(wvh, fast_tanh(qv[i] + kv[j]), acc[i][j]);
        }
    }

    float* ob = out + ((size_t)b * LQ_ + q0) * LK_ + k0;
#pragma unroll
    for (int i = 0; i < 2; i++)
#pragma unroll
        for (int j = 0; j < 4; j++)
            ob[(size_t)(ty + 16 * i) * LK_ + tx + 16 * j] = acc[i][j];
}

// ---------------------------------------------------------------------------

extern "C" void kernel_launch(void* const* d_in, const int* in_sizes, int n_in,
                              void* d_out, int out_size)
{
    const float* qs = (const float*)d_in[0];   // [8,512,512]
    const float* ks = (const float*)d_in[1];   // [8,512,512]
    const float* Wq = (const float*)d_in[2];   // [512,128]
    const float* Wk = (const float*)d_in[3];   // [512,128]
    const float* wv = (const float*)d_in[4];   // [128]
    float* out = (float*)d_out;                // [8,512,512]

    proj_kernel<<<2 * (M_ / BM), 512>>>(qs, ks, Wq, Wk);

    dim3 grid(LK_ / TK, LQ_ / TQ, B_);
    score_kernel<<<grid, 256>>>(wv, out);
}

// round 10
// speedup vs baseline: 1.3441x; 1.1661x over previous
#include <cuda_runtime.h>
#include <cuda_bf16.h>
#include <cstdint>

// Problem constants
#define B_   8
#define LQ_  512
#define LK_  512
#define D_   512
#define H_   128
#define M_   (B_ * LQ_)   // 4096 rows per projection

#define H_TANH 80        // h in [0,80): MUFU tanh path
#define H_EXP  48        // h in [80,128): exp-product + fma-pipe reciprocal path

// Scratch (no cudaMalloc allowed)
__device__ float g_Q[M_ * H_];
__device__ float g_K[M_ * H_];
__device__ float g_EQ[M_ * H_];   // e^{2q}
__device__ float g_EK[M_ * H_];   // e^{2k}

__device__ __forceinline__ float fast_tanh(float x) {
    float y;
    asm("tanh.approx.f32 %0, %1;" : "=f"(y) : "f"(x));
    return y;
}
__device__ __forceinline__ float fast_ex2(float x) {
    float y;
    asm("ex2.approx.f32 %0, %1;" : "=f"(y) : "f"(x));
    return y;
}

typedef unsigned long long ull;
__device__ __forceinline__ ull fma2_(ull a, ull b, ull c) {
    ull d; asm("fma.rn.f32x2 %0, %1, %2, %3;" : "=l"(d) : "l"(a), "l"(b), "l"(c)); return d;
}
__device__ __forceinline__ ull mul2_(ull a, ull b) {
    ull d; asm("mul.rn.f32x2 %0, %1, %2;" : "=l"(d) : "l"(a), "l"(b)); return d;
}
__device__ __forceinline__ ull add2_(ull a, ull b) {
    ull d; asm("add.rn.f32x2 %0, %1, %2;" : "=l"(d) : "l"(a), "l"(b)); return d;
}
__device__ __forceinline__ ull pack2(float lo, float hi) {
    ull p; asm("mov.b64 %0, {%1, %2};" : "=l"(p) : "f"(lo), "f"(hi)); return p;
}
__device__ __forceinline__ void unpack2(ull p, float& lo, float& hi) {
    asm("mov.b64 {%0, %1}, %2;" : "=f"(lo), "=f"(hi) : "l"(p));
}

// ---------------------------------------------------------------------------
// Projection GEMM (R3 config, plateaued ~32us): BM=64, BK=16, BN=128,
// 256 thr, 128 blocks, FFMA2 inner, reg prefetch. Epilogue additionally
// stores e^{2y} for the exp-path h's.
// ---------------------------------------------------------------------------
#define BM 64
#define BK 16
#define BN 128
#define APAD 8

__global__ __launch_bounds__(256) void proj_kernel(
    const float* __restrict__ qs, const float* __restrict__ ks,
    const float* __restrict__ Wq, const float* __restrict__ Wk)
{
    const int nb = M_ / BM;
    bool isK = (blockIdx.x >= nb);
    int bm = isK ? (blockIdx.x - nb) : blockIdx.x;
    const float* __restrict__ X = isK ? ks : qs;
    const float* __restrict__ W = isK ? Wk : Wq;
    float* __restrict__ Y = isK ? g_K : g_Q;
    float* __restrict__ E = isK ? g_EK : g_EQ;

    __shared__ float As[BK][BM + APAD];
    __shared__ float Bs[BK][BN];

    int tid = threadIdx.x;
    int tx = tid & 31;
    int ty = tid >> 5;
    int ar  = tid >> 2, ac4 = tid & 3;
    int br  = tid >> 5, bc4 = tid & 31;

    const float* Xp  = X + (size_t)(bm * BM + ar) * D_ + ac4 * 4;
    const float* Wp0 = W + (size_t)br * BN + bc4 * 4;
    const float* Wp1 = W + (size_t)(br + 8) * BN + bc4 * 4;

    ull acc2[4][4];
#pragma unroll
    for (int i = 0; i < 4; i++)
#pragma unroll
        for (int j = 0; j < 4; j++) acc2[i][j] = 0ull;

    float4 pa  = *(const float4*)(Xp);
    float4 pb0 = *(const float4*)(Wp0);
    float4 pb1 = *(const float4*)(Wp1);

    for (int k0 = 0; k0 < D_; k0 += BK) {
        As[ac4 * 4 + 0][ar] = pa.x;
        As[ac4 * 4 + 1][ar] = pa.y;
        As[ac4 * 4 + 2][ar] = pa.z;
        As[ac4 * 4 + 3][ar] = pa.w;
        *(float4*)(&Bs[br][bc4 * 4])     = pb0;
        *(float4*)(&Bs[br + 8][bc4 * 4]) = pb1;
        __syncthreads();

        if (k0 + BK < D_) {
            pa  = *(const float4*)(Xp + k0 + BK);
            pb0 = *(const float4*)(Wp0 + (size_t)(k0 + BK) * BN);
            pb1 = *(const float4*)(Wp1 + (size_t)(k0 + BK) * BN);
        }

#pragma unroll
        for (int kk = 0; kk < BK; ++kk) {
            ulonglong2 a01 = *(const ulonglong2*)(&As[kk][ty * 8]);
            ulonglong2 a23 = *(const ulonglong2*)(&As[kk][ty * 8 + 4]);
            ull ap[4] = {a01.x, a01.y, a23.x, a23.y};
            float4 bv = *(const float4*)(&Bs[kk][tx * 4]);
            ull bd[4] = {pack2(bv.x, bv.x), pack2(bv.y, bv.y),
                         pack2(bv.z, bv.z), pack2(bv.w, bv.w)};
#pragma unroll
            for (int i = 0; i < 4; i++)
#pragma unroll
                for (int j = 0; j < 4; j++)
                    acc2[i][j] = fma2_(ap[i], bd[j], acc2[i][j]);
        }
        __syncthreads();
    }

    const float LOG2E2 = 2.8853900817779268f;   // 2*log2(e)
#pragma unroll
    for (int i = 0; i < 4; i++) {
        float lo[4], hi[4];
#pragma unroll
        for (int j = 0; j < 4; j++) unpack2(acc2[i][j], lo[j], hi[j]);
        size_t r0 = (size_t)(bm * BM + ty * 8 + 2 * i) * H_ + tx * 4;
        *(float4*)(Y + r0)      = make_float4(lo[0], lo[1], lo[2], lo[3]);
        *(float4*)(Y + r0 + H_) = make_float4(hi[0], hi[1], hi[2], hi[3]);
        // exp(2y) for the exp path (cols >= H_TANH actually used; store all)
        float4 el = make_float4(fast_ex2(lo[0] * LOG2E2), fast_ex2(lo[1] * LOG2E2),
                                fast_ex2(lo[2] * LOG2E2), fast_ex2(lo[3] * LOG2E2));
        float4 eh = make_float4(fast_ex2(hi[0] * LOG2E2), fast_ex2(hi[1] * LOG2E2),
                                fast_ex2(hi[2] * LOG2E2), fast_ex2(hi[3] * LOG2E2));
        *(float4*)(E + r0)      = el;
        *(float4*)(E + r0 + H_) = eh;
    }
}

// ---------------------------------------------------------------------------
// Score kernel, dual-pipe:
//   pass A (h 0..79):   acc += wv*tanh(q+k)            — MUFU-bound
//   pass B (h 80..127): tanh = 1 - 2/(Eq*Ek + 1)       — fma-pipe recip
// out = accA + ws + 2*sum(wv*m), m = -1/(E+1) via magic seed + 2 Newton iters.
// 32q x 64k tiles, 256 threads, 1024 blocks.
// ---------------------------------------------------------------------------
#define TQ 32
#define TK 64
#define SSTR 82   // smem row stride (even -> 8B-aligned rows, conflict-free cols)

__global__ __launch_bounds__(256, 4) void score_kernel(
    const float* __restrict__ wv, float* __restrict__ out)
{
    __shared__ float s_q[TQ][SSTR];
    __shared__ float s_k[TK][SSTR];
    __shared__ float swv[H_];

    int b  = blockIdx.z;
    int q0 = blockIdx.y * TQ;
    int k0 = blockIdx.x * TK;

    int tid = threadIdx.x;
    int tx = tid & 15;
    int ty = tid >> 4;

    if (tid < H_) swv[tid] = wv[tid];

    const size_t qoff = (size_t)(b * LQ_ + q0) * H_;
    const size_t koff = (size_t)(b * LK_ + k0) * H_;

    float accA[2][4];
    ull   accB[2][4];
#pragma unroll
    for (int i = 0; i < 2; i++)
#pragma unroll
        for (int j = 0; j < 4; j++) { accA[i][j] = 0.f; accB[i][j] = 0ull; }

    // ---------------- pass A: tanh path, h in [0, 80) ----------------
    __syncthreads();
    {
        const float* Qb = g_Q + qoff;
        const float* Kb = g_K + koff;
        for (int i = tid; i < TQ * 20; i += 256) {
            int r = i / 20, c = i % 20;
            float4 v = *(const float4*)(Qb + r * H_ + c * 4);
            *(float2*)(&s_q[r][c * 4])     = make_float2(v.x, v.y);
            *(float2*)(&s_q[r][c * 4 + 2]) = make_float2(v.z, v.w);
        }
        for (int i = tid; i < TK * 20; i += 256) {
            int r = i / 20, c = i % 20;
            float4 v = *(const float4*)(Kb + r * H_ + c * 4);
            *(float2*)(&s_k[r][c * 4])     = make_float2(v.x, v.y);
            *(float2*)(&s_k[r][c * 4 + 2]) = make_float2(v.z, v.w);
        }
    }
    __syncthreads();

#pragma unroll 4
    for (int h = 0; h < H_TANH; ++h) {
        float wvh = swv[h];
        float qv[2], kv[4];
#pragma unroll
        for (int i = 0; i < 2; i++) qv[i] = s_q[ty + 16 * i][h];
#pragma unroll
        for (int j = 0; j < 4; j++) kv[j] = s_k[tx + 16 * j][h];
#pragma unroll
        for (int i = 0; i < 2; i++)
#pragma unroll
            for (int j = 0; j < 4; j++)
                accA[i][j] = fmaf(wvh, fast_tanh(qv[i] + kv[j]), accA[i][j]);
    }

    // ---------------- pass B: exp path, h in [80, 128) ----------------
    __syncthreads();
    {
        const float* Qb = g_EQ + qoff + H_TANH;
        const float* Kb = g_EK + koff + H_TANH;
        for (int i = tid; i < TQ * 12; i += 256) {
            int r = i / 12, c = i % 12;
            float4 v = *(const float4*)(Qb + r * H_ + c * 4);
            *(float2*)(&s_q[r][c * 4])     = make_float2(v.x, v.y);
            *(float2*)(&s_q[r][c * 4 + 2]) = make_float2(v.z, v.w);
        }
        for (int i = tid; i < TK * 12; i += 256) {
            int r = i / 12, c = i % 12;
            float4 v = *(const float4*)(Kb + r * H_ + c * 4);
            *(float2*)(&s_k[r][c * 4])     = make_float2(v.x, v.y);
            *(float2*)(&s_k[r][c * 4 + 2]) = make_float2(v.z, v.w);
        }
    }
    __syncthreads();

    const ull ONE2 = pack2(1.0f, 1.0f);
    const ull TWO2 = pack2(2.0f, 2.0f);

#pragma unroll 2
    for (int h2 = 0; h2 < H_EXP / 2; ++h2) {
        float2 wf = *(const float2*)(&swv[H_TANH + 2 * h2]);
        ull wv2 = pack2(wf.x, wf.y);
        ull Eq2[2], Ek2[4];
#pragma unroll
        for (int i = 0; i < 2; i++) {
            float2 v = *(const float2*)(&s_q[ty + 16 * i][2 * h2]);
            Eq2[i] = pack2(v.x, v.y);
        }
#pragma unroll
        for (int j = 0; j < 4; j++) {
            float2 v = *(const float2*)(&s_k[tx + 16 * j][2 * h2]);
            Ek2[j] = pack2(v.x, v.y);
        }
#pragma unroll
        for (int i = 0; i < 2; i++)
#pragma unroll
            for (int j = 0; j < 4; j++) {
                ull E = mul2_(Eq2[i], Ek2[j]);
                ull d = add2_(E, ONE2);
                float dx, dy;
                unpack2(d, dx, dy);
                // m0 = -1/d seed: bits(-x) trick folded into the magic
                float mx = __uint_as_float(0xFEF311C3u - __float_as_uint(dx));
                float my = __uint_as_float(0xFEF311C3u - __float_as_uint(dy));
                ull m = pack2(mx, my);
                // Newton on m = -r: u = 2 + d*m (= 2 - d*r); m' = m*u
                ull u = fma2_(d, m, TWO2);
                m = mul2_(m, u);
                u = fma2_(d, m, TWO2);
                m = mul2_(m, u);
                accB[i][j] = fma2_(wv2, m, accB[i][j]);
            }
    }

    // ws = sum of wv over exp h's
    float ws = 0.f;
#pragma unroll
    for (int h = H_TANH; h < H_; ++h) ws += swv[h];

    float* ob = out + ((size_t)b * LQ_ + q0) * LK_ + k0;
#pragma unroll
    for (int i = 0; i < 2; i++)
#pragma unroll
        for (int j = 0; j < 4; j++) {
            float mx, my;
            unpack2(accB[i][j], mx, my);
            float val = accA[i][j] + ws + 2.0f * (mx + my);
            ob[(size_t)(ty + 16 * i) * LK_ + tx + 16 * j] = val;
        }
}

// ---------------------------------------------------------------------------

extern "C" void kernel_launch(void* const* d_in, const int* in_sizes, int n_in,
                              void* d_out, int out_size)
{
    const float* qs = (const float*)d_in[0];   // [8,512,512]
    const float* ks = (const float*)d_in[1];   // [8,512,512]
    const float* Wq = (const float*)d_in[2];   // [512,128]
    const float* Wk = (const float*)d_in[3];   // [512,128]
    const float* wv = (const float*)d_in[4];   // [128]
    float* out = (float*)d_out;                // [8,512,512]

    proj_kernel<<<2 * (M_ / BM), 256>>>(qs, ks, Wq, Wk);

    dim3 grid(LK_ / TK, LQ_ / TQ, B_);
    score_kernel<<<grid, 256>>>(wv, out);
}